// round 6
// baseline (speedup 1.0000x reference)
#include <cuda_runtime.h>
#include <cuda_fp16.h>
#include <cuda_bf16.h>
#include <cstdint>

#define NN 256
#define AA 1024
#define BB 64
#define CC 16
#define NW 1024   // B*C

// GEMM tiling: 32x64 block tile, BK=32, full K=1024 per block, 3-stage cp.async
#define BM 32
#define BN 64
#define BK 32
#define NCHUNK (AA / BK)   // 32
#define NSTAGE 3
#define SAS 36    // sA row stride in floats (32+4): bank = (4*row+col)&31 -> conflict-free frags
#define SBS 72    // sB row stride in floats (64+8): bank = (8*k+n)&31   -> conflict-free frags

// Intermediate mat = (x @ W) * log2(e), fp16. 512 KB device scratch (no allocs allowed).
__device__ __half g_math[NN * NW];

// ---------------------------------------------------------------------------
// helpers
// ---------------------------------------------------------------------------
__device__ __forceinline__ uint32_t smem_u32(const void* p) {
    return (uint32_t)__cvta_generic_to_shared(p);
}
__device__ __forceinline__ void cpa16(uint32_t dst, const void* src) {
    asm volatile("cp.async.cg.shared.global [%0], [%1], 16;\n" :: "r"(dst), "l"(src));
}
__device__ __forceinline__ void cpa_commit() {
    asm volatile("cp.async.commit_group;\n" ::: "memory");
}
template <int N>
__device__ __forceinline__ void cpa_wait() {
    asm volatile("cp.async.wait_group %0;\n" :: "n"(N) : "memory");
}
// m16n8k8 tf32 mma; operands are fp32 bit patterns (HW truncates to tf32).
__device__ __forceinline__ void mma_tf32(float* c,
                                         uint32_t a0, uint32_t a1, uint32_t a2, uint32_t a3,
                                         uint32_t b0, uint32_t b1) {
    asm volatile("mma.sync.aligned.m16n8k8.row.col.f32.tf32.tf32.f32 "
                 "{%0,%1,%2,%3}, {%4,%5,%6,%7}, {%8,%9}, {%0,%1,%2,%3};\n"
                 : "+f"(c[0]), "+f"(c[1]), "+f"(c[2]), "+f"(c[3])
                 : "r"(a0), "r"(a1), "r"(a2), "r"(a3), "r"(b0), "r"(b1));
}
__device__ __forceinline__ float ex2f(float x) {
    float y; asm("ex2.approx.ftz.f32 %0, %1;" : "=f"(y) : "f"(x)); return y;
}

// ---------------------------------------------------------------------------
// Kernel 1: TF32 tensor-core GEMM directly on fp32 inputs.
// 256 threads = 8 warps in a 2(m) x 4(n) grid; warp tile 16x16 (2 x m16n8k8 per kstep).
// 3-stage cp.async pipeline, one __syncthreads per chunk.
// Epilogue scales by log2(e) and writes fp16 to g_math. Grid (16, 8) = 128 blocks.
// ---------------------------------------------------------------------------
__global__ __launch_bounds__(256) void md_gemm_kernel(const float* __restrict__ x,
                                                      const float* __restrict__ w) {
    __shared__ alignas(16) float sA[NSTAGE][BM][SAS];   // [stage][m][k]
    __shared__ alignas(16) float sB[NSTAGE][BK][SBS];   // [stage][k][n]

    const int t    = threadIdx.x;
    const int lane = t & 31;
    const int wid  = t >> 5;
    const int bm   = blockIdx.y * BM;
    const int bn   = blockIdx.x * BN;
    const int wm   = (wid >> 2) * 16;     // 0 or 16
    const int wn   = (wid & 3) * 16;      // 0,16,32,48
    const int g    = lane >> 2;           // 0..7
    const int tg   = lane & 3;            // 0..3

    // cp.async mapping: A 32x32 floats = 256 x 16B (1/thread); B 32x64 = 512 x 16B (2/thread)
    const int arow = t >> 3, aseg = (t & 7) * 4;
    const int krow = t >> 3, nseg = (t & 7) * 4;
    const float* xg = x + (size_t)(bm + arow) * AA + aseg;
    const float* wg = w + (size_t)krow * NW + bn + nseg;

    auto prefetch = [&](int ck, int st) {
        cpa16(smem_u32(&sA[st][arow][aseg]), xg + ck * BK);
        const float* wp = wg + (size_t)ck * BK * NW;
        cpa16(smem_u32(&sB[st][krow][nseg]),      wp);
        cpa16(smem_u32(&sB[st][krow][nseg + 32]), wp + 32);
        cpa_commit();
    };

    float acc[2][4] = {};

    prefetch(0, 0);
    prefetch(1, 1);

    int st = 0;
    for (int ck = 0; ck < NCHUNK; ck++) {
        if (ck + 1 < NCHUNK) cpa_wait<1>(); else cpa_wait<0>();
        __syncthreads();
        if (ck + 2 < NCHUNK) {
            int stn = st + 2; if (stn >= NSTAGE) stn -= NSTAGE;
            prefetch(ck + 2, stn);
        }

        #pragma unroll
        for (int k = 0; k < BK; k += 8) {
            const uint32_t* A0 = reinterpret_cast<const uint32_t*>(&sA[st][wm + g][k + tg]);
            uint32_t a0 = A0[0];
            uint32_t a1 = A0[8 * SAS];
            uint32_t a2 = A0[4];
            uint32_t a3 = A0[8 * SAS + 4];
            #pragma unroll
            for (int nt = 0; nt < 2; nt++) {
                const uint32_t* B0 =
                    reinterpret_cast<const uint32_t*>(&sB[st][k + tg][wn + nt * 8 + g]);
                uint32_t b0 = B0[0];
                uint32_t b1 = B0[4 * SBS];
                mma_tf32(acc[nt], a0, a1, a2, a3, b0, b1);
            }
        }
        if (++st == NSTAGE) st = 0;
    }

    // epilogue: c0/c1 at (row g, cols 2tg,2tg+1), c2/c3 at row g+8; scale by log2(e)
    const float S = 1.44269504f;
    const int row0 = bm + wm + g;
    #pragma unroll
    for (int nt = 0; nt < 2; nt++) {
        const int col = bn + wn + nt * 8 + 2 * tg;
        *reinterpret_cast<__half2*>(&g_math[row0 * NW + col]) =
            __floats2half2_rn(acc[nt][0] * S, acc[nt][1] * S);
        *reinterpret_cast<__half2*>(&g_math[(row0 + 8) * NW + col]) =
            __floats2half2_rn(acc[nt][2] * S, acc[nt][3] * S);
    }
}

// ---------------------------------------------------------------------------
// Kernel 2: pairwise exp2(-L1') in packed fp16.
// Block = (b, j-half). 1024 threads: j = t&127, i-range split 8 ways (t>>7).
// Grid (64, 2) = 128 blocks; smem tree reduce.
// ---------------------------------------------------------------------------
__global__ __launch_bounds__(1024) void md_pairwise_kernel(const float* __restrict__ bias,
                                                           float* __restrict__ out) {
    __shared__ __half sh[NN][CC];   // 8 KB
    __shared__ float red[1024];

    const int b  = blockIdx.x;
    const int jh = blockIdx.y;
    const int t  = threadIdx.x;

    if (t < NN) {   // stage mat[:, b, :] — one 32B row per thread
        const uint4* src = reinterpret_cast<const uint4*>(g_math + t * NW + b * CC);
        uint4* dst = reinterpret_cast<uint4*>(sh[t]);
        dst[0] = src[0];
        dst[1] = src[1];
    }
    __syncthreads();

    const int j  = jh * 128 + (t & 127);
    const int i0 = (t >> 7) * 32;

    __half2 m[8];
    #pragma unroll
    for (int c = 0; c < 8; c++) m[c] = reinterpret_cast<const __half2*>(sh[j])[c];

    float tot0 = 0.f, tot1 = 0.f;
    #pragma unroll 4
    for (int i = i0; i < i0 + 32; i += 2) {
        {
            const __half2* v = reinterpret_cast<const __half2*>(sh[i]);
            __half2 d0 = __hsub2(m[0], v[0]), d1 = __hsub2(m[1], v[1]);
            __half2 d2 = __hsub2(m[2], v[2]), d3 = __hsub2(m[3], v[3]);
            __half2 d4 = __hsub2(m[4], v[4]), d5 = __hsub2(m[5], v[5]);
            __half2 d6 = __hsub2(m[6], v[6]), d7 = __hsub2(m[7], v[7]);
            __half2 s0 = __hadd2(__habs2(d0), __habs2(d1));
            __half2 s1 = __hadd2(__habs2(d2), __habs2(d3));
            __half2 s2 = __hadd2(__habs2(d4), __habs2(d5));
            __half2 s3 = __hadd2(__habs2(d6), __habs2(d7));
            __half2 L  = __hadd2(__hadd2(s0, s1), __hadd2(s2, s3));
            tot0 += ex2f(-(__low2float(L) + __high2float(L)));
        }
        {
            const __half2* v = reinterpret_cast<const __half2*>(sh[i + 1]);
            __half2 d0 = __hsub2(m[0], v[0]), d1 = __hsub2(m[1], v[1]);
            __half2 d2 = __hsub2(m[2], v[2]), d3 = __hsub2(m[3], v[3]);
            __half2 d4 = __hsub2(m[4], v[4]), d5 = __hsub2(m[5], v[5]);
            __half2 d6 = __hsub2(m[6], v[6]), d7 = __hsub2(m[7], v[7]);
            __half2 s0 = __hadd2(__habs2(d0), __habs2(d1));
            __half2 s1 = __hadd2(__habs2(d2), __habs2(d3));
            __half2 s2 = __hadd2(__habs2(d4), __habs2(d5));
            __half2 s3 = __hadd2(__habs2(d6), __habs2(d7));
            __half2 L  = __hadd2(__hadd2(s0, s1), __hadd2(s2, s3));
            tot1 += ex2f(-(__low2float(L) + __high2float(L)));
        }
    }

    red[t] = tot0 + tot1;
    __syncthreads();
    if (t < 128) {
        float s = red[t];
        #pragma unroll
        for (int q = 1; q < 8; q++) s += red[t + q * 128];
        out[j * BB + b] = s + bias[b];
    }
}

// ---------------------------------------------------------------------------
// Launch. Inputs: x [N*A] f32, weight [A*B*C] f32, bias [B] f32. Output [N,B] f32.
// ---------------------------------------------------------------------------
extern "C" void kernel_launch(void* const* d_in, const int* in_sizes, int n_in,
                              void* d_out, int out_size) {
    const float* x    = (const float*)d_in[0];
    const float* w    = (const float*)d_in[1];
    const float* bias = (const float*)d_in[2];
    float* out = (float*)d_out;

    md_gemm_kernel<<<dim3(NW / BN, NN / BM), 256>>>(x, w);
    md_pairwise_kernel<<<dim3(BB, 2), 1024>>>(bias, out);
}

// round 7
// speedup vs baseline: 1.2132x; 1.2132x over previous
#include <cuda_runtime.h>
#include <cuda_fp16.h>
#include <cuda_bf16.h>
#include <cstdint>

#define NN 256
#define AA 1024
#define BB 64
#define CC 16
#define NW 1024   // B*C

// GEMM tiling (R5 bf16 split-K configuration)
#define BM 32
#define BN 64
#define BK 32
#define KSPLIT 2
#define KHALF (AA / KSPLIT)     // 512
#define NCH   (KHALF / BK)      // 16
#define SAS 40
#define SBS 72

// Device scratch: bf16 copies of inputs + fp16 mat*log2e
__device__ __nv_bfloat16 g_xb[NN * AA];     // 512 KB
__device__ __nv_bfloat16 g_wb[AA * NW];     //   2 MB
__device__ __half        g_math[NN * NW];   // 512 KB

// tile-pair enumeration for the symmetric pairwise phase (ti <= tj, 64-row tiles)
__constant__ int c_ti[10] = {0,0,0,0,1,1,1,2,2,3};
__constant__ int c_tj[10] = {0,1,2,3,1,2,3,2,3,3};

// ---------------------------------------------------------------------------
// helpers
// ---------------------------------------------------------------------------
__device__ __forceinline__ uint32_t pack_bf2(float a, float b) {
    __nv_bfloat162 h = __floats2bfloat162_rn(a, b);
    return *reinterpret_cast<uint32_t*>(&h);
}
__device__ __forceinline__ uint32_t smem_u32(const void* p) {
    return (uint32_t)__cvta_generic_to_shared(p);
}
__device__ __forceinline__ void cpa16(uint32_t dst, const void* src) {
    asm volatile("cp.async.cg.shared.global [%0], [%1], 16;\n" :: "r"(dst), "l"(src));
}
__device__ __forceinline__ void cpa_commit() {
    asm volatile("cp.async.commit_group;\n" ::: "memory");
}
template <int N>
__device__ __forceinline__ void cpa_wait() {
    asm volatile("cp.async.wait_group %0;\n" :: "n"(N) : "memory");
}
__device__ __forceinline__ void ldsm_x4(uint32_t& r0, uint32_t& r1,
                                        uint32_t& r2, uint32_t& r3, uint32_t addr) {
    asm volatile("ldmatrix.sync.aligned.m8n8.x4.shared.b16 {%0,%1,%2,%3}, [%4];\n"
                 : "=r"(r0), "=r"(r1), "=r"(r2), "=r"(r3) : "r"(addr));
}
__device__ __forceinline__ void ldsm_x4_t(uint32_t& r0, uint32_t& r1,
                                          uint32_t& r2, uint32_t& r3, uint32_t addr) {
    asm volatile("ldmatrix.sync.aligned.m8n8.x4.trans.shared.b16 {%0,%1,%2,%3}, [%4];\n"
                 : "=r"(r0), "=r"(r1), "=r"(r2), "=r"(r3) : "r"(addr));
}
__device__ __forceinline__ void mma16816(float* c,
                                         uint32_t a0, uint32_t a1, uint32_t a2, uint32_t a3,
                                         uint32_t b0, uint32_t b1) {
    asm volatile("mma.sync.aligned.m16n8k16.row.col.f32.bf16.bf16.f32 "
                 "{%0,%1,%2,%3}, {%4,%5,%6,%7}, {%8,%9}, {%0,%1,%2,%3};\n"
                 : "+f"(c[0]), "+f"(c[1]), "+f"(c[2]), "+f"(c[3])
                 : "r"(a0), "r"(a1), "r"(a2), "r"(a3), "r"(b0), "r"(b1));
}
__device__ __forceinline__ float ex2f(float x) {
    float y; asm("ex2.approx.ftz.f32 %0, %1;" : "=f"(y) : "f"(x)); return y;
}

// ---------------------------------------------------------------------------
// Kernel 0: fp32 -> bf16 conversion, high-MLP version.
// 32 elems/thread: 8 front-batched coalesced LDG.128, 8 STG.64.
// Blocks 0..31 -> x (262144 elems), 32..159 -> w (1048576 elems).
// ---------------------------------------------------------------------------
__global__ __launch_bounds__(256) void md_cvt_kernel(const float* __restrict__ x,
                                                     const float* __restrict__ w) {
    const int bid = blockIdx.x;
    const float* src;
    __nv_bfloat16* dst;
    int base;
    if (bid < 32) { src = x; dst = g_xb; base = bid * 8192; }
    else          { src = w; dst = g_wb; base = (bid - 32) * 8192; }

    const int off = threadIdx.x * 4;
    float4 v[8];
    #pragma unroll
    for (int q = 0; q < 8; q++)
        v[q] = *(const float4*)(src + base + q * 1024 + off);
    #pragma unroll
    for (int q = 0; q < 8; q++) {
        uint2 p;
        p.x = pack_bf2(v[q].x, v[q].y);
        p.y = pack_bf2(v[q].z, v[q].w);
        *reinterpret_cast<uint2*>(dst + base + q * 1024 + off) = p;
    }
}

// ---------------------------------------------------------------------------
// Kernel 1: bf16 tensor-core GEMM (R5 structure), 256 threads = 2 K-groups x 4 warps.
// Epilogue scales by log2(e), writes fp16 to g_math, and (blockIdx.x==0) seeds
// out[] with bias so the pairwise kernel can accumulate atomically.
// ---------------------------------------------------------------------------
__global__ __launch_bounds__(256) void md_gemm_kernel(const float* __restrict__ bias,
                                                      float* __restrict__ out) {
    __shared__ alignas(16) __nv_bfloat16 sA[KSPLIT][2][BM][SAS];
    __shared__ alignas(16) __nv_bfloat16 sB[KSPLIT][2][BK][SBS];
    __shared__ float red[BM][BN + 1];

    const int t    = threadIdx.x;
    const int lane = t & 31;
    const int wid  = t >> 5;
    const int g    = wid >> 2;
    const int wl   = wid & 3;
    const int bm   = blockIdx.y * BM;
    const int bn   = blockIdx.x * BN;
    const int wm   = (wl >> 1) * 16;
    const int wn   = (wl & 1) * 32;
    const int tg   = t & 127;

    const int arow  = tg >> 2, aseg = tg & 3;
    const int brow0 = tg >> 3, bseg = tg & 7;
    const int brow1 = brow0 + 16;
    const __nv_bfloat16* xa = g_xb + (size_t)(bm + arow) * AA + g * KHALF + aseg * 8;
    const __nv_bfloat16* wb = g_wb + (size_t)(g * KHALF) * NW + bn + bseg * 8;

    const uint32_t dA  = smem_u32(&sA[g][0][arow][aseg * 8]);
    const uint32_t dB0 = smem_u32(&sB[g][0][brow0][bseg * 8]);
    const uint32_t dB1 = smem_u32(&sB[g][0][brow1][bseg * 8]);
    const uint32_t aBuf = sizeof(__nv_bfloat16) * BM * SAS;
    const uint32_t bBuf = sizeof(__nv_bfloat16) * BK * SBS;

    auto prefetch = [&](int ck, int buf) {
        cpa16(dA  + buf * aBuf, xa + (size_t)ck * BK);
        const __nv_bfloat16* wp = wb + (size_t)ck * BK * NW;
        cpa16(dB0 + buf * bBuf, wp + (size_t)brow0 * NW);
        cpa16(dB1 + buf * bBuf, wp + (size_t)brow1 * NW);
    };

    float acc[4][4] = {};
    const int lr = lane & 15;
    const int lc = (lane >> 4) * 8;

    prefetch(0, 0);
    cpa_commit();

    for (int ck = 0; ck < NCH; ck++) {
        const int buf = ck & 1;
        if (ck + 1 < NCH) {
            prefetch(ck + 1, buf ^ 1);
            cpa_commit();
            cpa_wait<1>();
        } else {
            cpa_wait<0>();
        }
        __syncthreads();

        #pragma unroll
        for (int kk = 0; kk < BK; kk += 16) {
            uint32_t a0, a1, a2, a3;
            ldsm_x4(a0, a1, a2, a3, smem_u32(&sA[g][buf][wm + lr][kk + lc]));
            #pragma unroll
            for (int nb = 0; nb < 2; nb++) {
                uint32_t b0, b1, b2, b3;
                ldsm_x4_t(b0, b1, b2, b3,
                          smem_u32(&sB[g][buf][kk + lr][wn + nb * 16 + lc]));
                mma16816(acc[nb * 2 + 0], a0, a1, a2, a3, b0, b1);
                mma16816(acc[nb * 2 + 1], a0, a1, a2, a3, b2, b3);
            }
        }
        __syncthreads();
    }

    const int r0 = wm + (lane >> 2);
    const int c0 = wn + (lane & 3) * 2;
    if (g == 1) {
        #pragma unroll
        for (int nt = 0; nt < 4; nt++) {
            red[r0][c0 + nt * 8]         = acc[nt][0];
            red[r0][c0 + nt * 8 + 1]     = acc[nt][1];
            red[r0 + 8][c0 + nt * 8]     = acc[nt][2];
            red[r0 + 8][c0 + nt * 8 + 1] = acc[nt][3];
        }
    }
    __syncthreads();
    if (g == 0) {
        const float S = 1.44269504f;   // exp(-l1) == exp2(-l1 * log2(e))
        #pragma unroll
        for (int nt = 0; nt < 4; nt++) {
            float v0 = (acc[nt][0] + red[r0][c0 + nt * 8])         * S;
            float v1 = (acc[nt][1] + red[r0][c0 + nt * 8 + 1])     * S;
            float v2 = (acc[nt][2] + red[r0 + 8][c0 + nt * 8])     * S;
            float v3 = (acc[nt][3] + red[r0 + 8][c0 + nt * 8 + 1]) * S;
            const int col = bn + c0 + nt * 8;
            *reinterpret_cast<__half2*>(&g_math[(bm + r0) * NW + col])     = __floats2half2_rn(v0, v1);
            *reinterpret_cast<__half2*>(&g_math[(bm + r0 + 8) * NW + col]) = __floats2half2_rn(v2, v3);
        }
    }

    // seed out[] with bias (out[j*BB + b] = bias[b]); 8 blocks x 256 thr x 8 elems
    if (blockIdx.x == 0) {
        const int e0 = (blockIdx.y * 256 + t) * 8;
        const float4* bsrc = reinterpret_cast<const float4*>(bias + (e0 & 63));
        float4* odst = reinterpret_cast<float4*>(out + e0);
        odst[0] = bsrc[0];
        odst[1] = bsrc[1];
    }
}

// ---------------------------------------------------------------------------
// Kernel 2: symmetric pairwise exp2(-L1').
// Grid (64 b, 10 tile-pairs). Tile = 64x64 over (i, j); off-diagonal tiles are
// computed once and credited to both row sums (j) and column sums (i).
// 512 threads: jl = t&63, iq = t>>6 -> 8 i's per thread. E-matrix in smem,
// two reduce passes, atomicAdd into bias-seeded out.
// ---------------------------------------------------------------------------
__global__ __launch_bounds__(512) void md_pairwise_kernel(float* __restrict__ out) {
    __shared__ __half shJ[64][16];      // rows of the j-tile
    __shared__ __half shI[64][16];      // rows of the i-tile
    __shared__ float Em[64][65];        // E[i][jl], padded
    __shared__ float Pbuf[512];

    const int b  = blockIdx.x;
    const int ti = c_ti[blockIdx.y];
    const int tj = c_tj[blockIdx.y];
    const int t  = threadIdx.x;

    if (t < 64) {
        const uint4* src = reinterpret_cast<const uint4*>(g_math + (tj * 64 + t) * NW + b * CC);
        uint4* dst = reinterpret_cast<uint4*>(shJ[t]);
        dst[0] = src[0]; dst[1] = src[1];
    } else if (t < 128) {
        const int r = t - 64;
        const uint4* src = reinterpret_cast<const uint4*>(g_math + (ti * 64 + r) * NW + b * CC);
        uint4* dst = reinterpret_cast<uint4*>(shI[r]);
        dst[0] = src[0]; dst[1] = src[1];
    }
    __syncthreads();

    const int jl = t & 63;
    const int iq = t >> 6;        // uniform within a warp -> shI loads broadcast

    __half2 m[8];
    #pragma unroll
    for (int c = 0; c < 8; c++) m[c] = reinterpret_cast<const __half2*>(shJ[jl])[c];

    float rs = 0.f;
    #pragma unroll
    for (int q = 0; q < 8; q++) {
        const int i = iq * 8 + q;
        const __half2* v = reinterpret_cast<const __half2*>(shI[i]);
        __half2 d0 = __hsub2(m[0], v[0]), d1 = __hsub2(m[1], v[1]);
        __half2 d2 = __hsub2(m[2], v[2]), d3 = __hsub2(m[3], v[3]);
        __half2 d4 = __hsub2(m[4], v[4]), d5 = __hsub2(m[5], v[5]);
        __half2 d6 = __hsub2(m[6], v[6]), d7 = __hsub2(m[7], v[7]);
        __half2 s0 = __hadd2(__habs2(d0), __habs2(d1));
        __half2 s1 = __hadd2(__habs2(d2), __habs2(d3));
        __half2 s2 = __hadd2(__habs2(d4), __habs2(d5));
        __half2 s3 = __hadd2(__habs2(d6), __habs2(d7));
        __half2 L  = __hadd2(__hadd2(s0, s1), __hadd2(s2, s3));
        float E = ex2f(-(__low2float(L) + __high2float(L)));
        rs += E;
        Em[i][jl] = E;
    }
    Pbuf[t] = rs;
    __syncthreads();

    // row sums -> out rows of the j-tile
    if (t < 64) {
        float s = Pbuf[t];
        #pragma unroll
        for (int q = 1; q < 8; q++) s += Pbuf[t + (q << 6)];
        atomicAdd(&out[(tj * 64 + t) * BB + b], s);
    }

    if (ti != tj) {
        __syncthreads();   // protect Pbuf reuse (block-uniform branch)
        const int ii = t >> 3, s8 = t & 7;
        float cs = 0.f;
        #pragma unroll
        for (int q = 0; q < 8; q++) cs += Em[ii][s8 * 8 + q];
        Pbuf[t] = cs;
        __syncthreads();
        // column sums -> out rows of the i-tile
        if (t < 64) {
            float s = Pbuf[t * 8];
            #pragma unroll
            for (int q = 1; q < 8; q++) s += Pbuf[t * 8 + q];
            atomicAdd(&out[(ti * 64 + t) * BB + b], s);
        }
    }
}

// ---------------------------------------------------------------------------
// Launch. Inputs: x [N*A] f32, weight [A*B*C] f32, bias [B] f32. Output [N,B] f32.
// ---------------------------------------------------------------------------
extern "C" void kernel_launch(void* const* d_in, const int* in_sizes, int n_in,
                              void* d_out, int out_size) {
    const float* x    = (const float*)d_in[0];
    const float* w    = (const float*)d_in[1];
    const float* bias = (const float*)d_in[2];
    float* out = (float*)d_out;

    md_cvt_kernel<<<160, 256>>>(x, w);
    md_gemm_kernel<<<dim3(NW / BN, NN / BM), 256>>>(bias, out);
    md_pairwise_kernel<<<dim3(BB, 10), 512>>>(out);
}